// round 15
// baseline (speedup 1.0000x reference)
#include <cuda_runtime.h>
#include <cuda_bf16.h>
#include <math.h>
#include <stdlib.h>
#include <stdint.h>

// ---------------------------------------------------------------------------
// BrainGCN: 2x GCNConv(+tanh) then 2 FC layers.
//   h1 = tanh( Ahat @ (x@W1)  + b1 )
//   h2 = tanh( Ahat @ (h1@W2) + b2 )
//   out = tanh(h2@W3 + b3) @ W4 + b4
// R15 (base = R14/R8 best config):
//  - detect_dtype folded into convert_count (one less launch)
//  - deg memset removed: scan_dinv re-zeros deg after use (replay-safe)
//  - gather2 + FC head fused into one warp-per-node kernel (saves the
//    25.6MB agg2 round trip + a launch)
//  => submission order convert,scan,fill,gemm1,gather1 puts gather1 at the
//     profiler's capture slot (pos 5) — first real gather profile.
// ---------------------------------------------------------------------------

namespace {
struct EnvInit {  // must run before any CUDA call (lazy-load workaround, R4)
    EnvInit() { setenv("CUDA_MODULE_LOADING", "EAGER", 1); }
};
EnvInit g_env_init;
}

#define MAX_NODES 50000
#define MAX_EDGES 800000

__device__ int   g_deg[MAX_NODES];          // zero-init at load; re-zeroed by scan
__device__ float g_dinv[MAX_NODES];
__device__ int   g_src[MAX_EDGES];
__device__ int   g_dst[MAX_EDGES];
__device__ int   g_rowptr[MAX_NODES + 1];
__device__ int   g_cursor[MAX_NODES];
__device__ int2  g_csr[MAX_EDGES];          // {src, __float_as_int(coef)}

// Aliasing: big1 = xw1[M,128], later xw2[M,64]. big2 = h1[M,128].
__device__ float g_big1[MAX_NODES * 128];
__device__ float g_big2[MAX_NODES * 128];

// ---------------------------------------------------------------------------
// Fast tanh: (e^2x - 1)/(e^2x + 1). Abs err ~2.4e-7 (measured neutral vs libm
// in accuracy; kept for lower instruction count).
// ---------------------------------------------------------------------------
__device__ __forceinline__ float fast_tanhf(float x) {
    float xc = fminf(fmaxf(x, -15.0f), 15.0f);
    float t = __expf(2.0f * xc);
    return __fdividef(t - 1.0f, t + 1.0f);
}

// ---------------------------------------------------------------------------
// Fused convert + degree count; per-block int64/int32 detection (two
// L2-broadcast lines). deg must be zero on entry (module init / prev scan).
// ---------------------------------------------------------------------------
__global__ void convert_count_kernel(const void* __restrict__ ei, int E) {
    const unsigned int* w = (const unsigned int*)ei;
    int is64 = 1;
    #pragma unroll
    for (int i = 0; i < 16; i++)
        if (w[2 * i + 1] != 0u) is64 = 0;

    int e = blockIdx.x * blockDim.x + threadIdx.x;
    if (e >= E) return;
    int s, d;
    if (is64) {
        s = (int)((const long long*)ei)[e];
        d = (int)((const long long*)ei)[E + e];
    } else {
        s = ((const int*)ei)[e];
        d = ((const int*)ei)[E + e];
    }
    g_src[e] = s;
    g_dst[e] = d;
    atomicAdd(&g_deg[d], 1);
}

// Single-block scan: deg -> rowptr/cursor + dinv; RE-ZEROS deg after reading
// so the next graph replay starts from a clean histogram.
__global__ void scan_dinv_kernel(int M, int E) {
    __shared__ int s[1024];
    const int t = threadIdx.x;
    const int CH = (M + 1023) / 1024;
    const int beg = t * CH;
    const int end = min(M, beg + CH);
    int loc = 0;
    for (int i = beg; i < end; i++) loc += g_deg[i];
    s[t] = loc;
    __syncthreads();
    for (int off = 1; off < 1024; off <<= 1) {
        int v = (t >= off) ? s[t - off] : 0;
        __syncthreads();
        s[t] += v;
        __syncthreads();
    }
    int run = s[t] - loc;
    for (int i = beg; i < end; i++) {
        int d = g_deg[i];
        g_rowptr[i] = run;
        g_cursor[i] = run;
        g_dinv[i] = rsqrtf((float)d + 1.0f);  // +1 self-loop
        g_deg[i] = 0;                          // ready for next replay
        run += d;
    }
    if (t == 1023) g_rowptr[M] = E;
}

__global__ void fill_kernel(int E) {
    int e = blockIdx.x * blockDim.x + threadIdx.x;
    if (e >= E) return;
    int s = g_src[e];
    int d = g_dst[e];
    int pos = atomicAdd(&g_cursor[d], 1);
    g_csr[pos] = make_int2(s, __float_as_int(g_dinv[s] * g_dinv[d]));
}

// ---------------------------------------------------------------------------
// Split-TF32 tensor-core GEMM (R8 layout): C[M,N] = A[M,K=128] @ W[128,N].
// 3-term compensated: C = Ah*Wh + Ah*Wl + Al*Wh.
// ---------------------------------------------------------------------------
__device__ __forceinline__ uint32_t f2tf32(float x) {
    uint32_t h;
    asm("cvt.rna.tf32.f32 %0, %1;" : "=r"(h) : "f"(x));
    return h;
}
__device__ __forceinline__ void split_tf32(float x, uint32_t& hi, uint32_t& lo) {
    hi = f2tf32(x);
    lo = f2tf32(x - __uint_as_float(hi));
}
__device__ __forceinline__ void mma_tf32(float* c, const uint32_t* a, uint32_t b0, uint32_t b1) {
    asm volatile(
        "mma.sync.aligned.m16n8k8.row.col.f32.tf32.tf32.f32 "
        "{%0,%1,%2,%3}, {%4,%5,%6,%7}, {%8,%9}, {%0,%1,%2,%3};"
        : "+f"(c[0]), "+f"(c[1]), "+f"(c[2]), "+f"(c[3])
        : "r"(a[0]), "r"(a[1]), "r"(a[2]), "r"(a[3]), "r"(b0), "r"(b1));
}

template <int N>
__global__ void __launch_bounds__(256)
gemm_tf32_kernel(const float* __restrict__ A, const float* __restrict__ W,
                 float* __restrict__ C, int M) {
    constexpr int K = 128;
    constexpr int LDW = N + 4;
    constexpr int NT = (N / 2) / 8;
    extern __shared__ __align__(16) float2 sW[];

    const int tid  = threadIdx.x;
    const int warp = tid >> 5;
    const int lane = tid & 31;

    for (int i = tid; i < K * N; i += 256) {
        const int k = i / N, n = i % N;
        float w = W[i];
        uint32_t h, l;
        split_tf32(w, h, l);
        sW[k * LDW + n] = make_float2(__uint_as_float(h), __uint_as_float(l));
    }
    __syncthreads();

    const int m0 = blockIdx.x * 128 + (warp >> 1) * 32;
    const int n0 = (warp & 1) * (N / 2);
    const int g  = lane >> 2;
    const int tg = lane & 3;

    const float* Arow[4];
    #pragma unroll
    for (int mt = 0; mt < 2; mt++) {
        int r0 = m0 + mt * 16 + g;
        Arow[mt * 2 + 0] = A + (long long)min(r0,     M - 1) * K;
        Arow[mt * 2 + 1] = A + (long long)min(r0 + 8, M - 1) * K;
    }

    float acc[2][NT][4];
    #pragma unroll
    for (int mt = 0; mt < 2; mt++)
        #pragma unroll
        for (int j = 0; j < NT; j++)
            #pragma unroll
            for (int q = 0; q < 4; q++) acc[mt][j][q] = 0.0f;

    const float2* wb = sW + tg * LDW + n0 + g;

    float acur[2][4], anxt[2][4];
    #pragma unroll
    for (int mt = 0; mt < 2; mt++) {
        acur[mt][0] = Arow[mt * 2 + 0][tg];
        acur[mt][1] = Arow[mt * 2 + 1][tg];
        acur[mt][2] = Arow[mt * 2 + 0][tg + 4];
        acur[mt][3] = Arow[mt * 2 + 1][tg + 4];
    }

    #pragma unroll
    for (int k0 = 0; k0 < K; k0 += 8) {
        if (k0 + 8 < K) {
            #pragma unroll
            for (int mt = 0; mt < 2; mt++) {
                anxt[mt][0] = Arow[mt * 2 + 0][k0 + 8 + tg];
                anxt[mt][1] = Arow[mt * 2 + 1][k0 + 8 + tg];
                anxt[mt][2] = Arow[mt * 2 + 0][k0 + 8 + tg + 4];
                anxt[mt][3] = Arow[mt * 2 + 1][k0 + 8 + tg + 4];
            }
        }

        uint32_t ah[2][4], al[2][4];
        #pragma unroll
        for (int mt = 0; mt < 2; mt++)
            #pragma unroll
            for (int q = 0; q < 4; q++)
                split_tf32(acur[mt][q], ah[mt][q], al[mt][q]);

        const float2* wk0 = wb + k0 * LDW;
        #pragma unroll
        for (int j = 0; j < NT; j++) {
            float2 w0 = wk0[j * 8];
            float2 w1 = wk0[4 * LDW + j * 8];
            uint32_t bh0 = __float_as_uint(w0.x), bl0 = __float_as_uint(w0.y);
            uint32_t bh1 = __float_as_uint(w1.x), bl1 = __float_as_uint(w1.y);
            #pragma unroll
            for (int mt = 0; mt < 2; mt++) {
                mma_tf32(acc[mt][j], ah[mt], bh0, bh1);
                mma_tf32(acc[mt][j], ah[mt], bl0, bl1);
                mma_tf32(acc[mt][j], al[mt], bh0, bh1);
            }
        }

        #pragma unroll
        for (int mt = 0; mt < 2; mt++)
            #pragma unroll
            for (int q = 0; q < 4; q++) acur[mt][q] = anxt[mt][q];
    }

    #pragma unroll
    for (int mt = 0; mt < 2; mt++) {
        int r0 = m0 + mt * 16 + g;
        #pragma unroll
        for (int j = 0; j < NT; j++) {
            int col = n0 + j * 8 + tg * 2;
            if (r0 < M)
                *reinterpret_cast<float2*>(C + (long long)r0 * N + col) =
                    make_float2(acc[mt][j][0], acc[mt][j][1]);
            if (r0 + 8 < M)
                *reinterpret_cast<float2*>(C + (long long)(r0 + 8) * N + col) =
                    make_float2(acc[mt][j][2], acc[mt][j][3]);
        }
    }
}

// ---------------------------------------------------------------------------
// Layer-1 CSR gather, one WARP per node, unroll x4, tanh fused (R7).
// ---------------------------------------------------------------------------
__global__ void __launch_bounds__(256)
gather1_kernel(const float* __restrict__ xw, const float* __restrict__ bias,
               float* __restrict__ out, int M) {
    constexpr int F = 128;
    const int gw   = (blockIdx.x * blockDim.x + threadIdx.x) >> 5;
    const int lane = threadIdx.x & 31;
    if (gw >= M) return;

    const float di = g_dinv[gw];
    const float cself = di * di;
    const int beg = g_rowptr[gw];
    const int end = g_rowptr[gw + 1];

    float4 v  = reinterpret_cast<const float4*>(xw + (long long)gw * F)[lane];
    float4 bb = reinterpret_cast<const float4*>(bias)[lane];
    float4 acc = make_float4(fmaf(v.x, cself, bb.x), fmaf(v.y, cself, bb.y),
                             fmaf(v.z, cself, bb.z), fmaf(v.w, cself, bb.w));
    int j = beg;
    for (; j + 4 <= end; j += 4) {
        int2 c0 = g_csr[j],     c1 = g_csr[j + 1];
        int2 c2 = g_csr[j + 2], c3 = g_csr[j + 3];
        float4 a0 = reinterpret_cast<const float4*>(xw + (long long)c0.x * F)[lane];
        float4 a1 = reinterpret_cast<const float4*>(xw + (long long)c1.x * F)[lane];
        float4 a2 = reinterpret_cast<const float4*>(xw + (long long)c2.x * F)[lane];
        float4 a3 = reinterpret_cast<const float4*>(xw + (long long)c3.x * F)[lane];
        float w0 = __int_as_float(c0.y), w1 = __int_as_float(c1.y);
        float w2 = __int_as_float(c2.y), w3 = __int_as_float(c3.y);
        acc.x = fmaf(a0.x, w0, fmaf(a1.x, w1, fmaf(a2.x, w2, fmaf(a3.x, w3, acc.x))));
        acc.y = fmaf(a0.y, w0, fmaf(a1.y, w1, fmaf(a2.y, w2, fmaf(a3.y, w3, acc.y))));
        acc.z = fmaf(a0.z, w0, fmaf(a1.z, w1, fmaf(a2.z, w2, fmaf(a3.z, w3, acc.z))));
        acc.w = fmaf(a0.w, w0, fmaf(a1.w, w1, fmaf(a2.w, w2, fmaf(a3.w, w3, acc.w))));
    }
    for (; j < end; j++) {
        int2 c0 = g_csr[j];
        float w0 = __int_as_float(c0.y);
        float4 a = reinterpret_cast<const float4*>(xw + (long long)c0.x * F)[lane];
        acc.x = fmaf(a.x, w0, acc.x);
        acc.y = fmaf(a.y, w0, acc.y);
        acc.z = fmaf(a.z, w0, acc.z);
        acc.w = fmaf(a.w, w0, acc.w);
    }
    acc.x = fast_tanhf(acc.x); acc.y = fast_tanhf(acc.y);
    acc.z = fast_tanhf(acc.z); acc.w = fast_tanhf(acc.w);
    reinterpret_cast<float4*>(out + (long long)gw * F)[lane] = acc;
}

// ---------------------------------------------------------------------------
// Fused gather2 + FC head, one WARP per node (loops over nodes to amortize
// W3 staging):
//   agg2 = gather(xw2) + dinv^2*xw2 + b2      (float2 per lane)
//   h    = tanh(agg2)           -> per-warp smem buffer
//   t_j  = b3_j + sum_k h_k W3[k][j]  (lane-parallel over j, j=lane & lane+32)
//   out  = sum_j tanh(t_j) W4_j + b4  (shfl reduce)
// Bank patterns: sW3[k*64+lane(+32)] consecutive -> conflict-free; h_k
// broadcast. hbuf private per warp -> __syncwarp ordering only.
// ---------------------------------------------------------------------------
__global__ void __launch_bounds__(256)
gather_fc_kernel(const float* __restrict__ xw2, const float* __restrict__ b2,
                 const float* __restrict__ W3, const float* __restrict__ b3,
                 const float* __restrict__ W4, const float* __restrict__ b4,
                 float* __restrict__ out, int M) {
    constexpr int F = 64;
    __shared__ __align__(16) float sW3[64 * 64];  // original layout W3[k*64+j]
    __shared__ float sb3[64];
    __shared__ float sW4[64];
    __shared__ float hbuf[8][64];

    const int tid = threadIdx.x;
    for (int i = tid; i < 64 * 64; i += 256) sW3[i] = W3[i];
    if (tid < 64) { sb3[tid] = b3[tid]; sW4[tid] = W4[tid]; }
    __syncthreads();

    const int warp = tid >> 5;
    const int lane = tid & 31;
    const float b4v = b4[0];
    const float2 bb = reinterpret_cast<const float2*>(b2)[lane];

    for (int node = blockIdx.x * 8 + warp; node < M; node += gridDim.x * 8) {
        const float di = g_dinv[node];
        const float cself = di * di;
        const int beg = g_rowptr[node];
        const int end = g_rowptr[node + 1];

        float2 v = reinterpret_cast<const float2*>(xw2 + (long long)node * F)[lane];
        float2 acc = make_float2(fmaf(v.x, cself, bb.x), fmaf(v.y, cself, bb.y));
        int j = beg;
        for (; j + 4 <= end; j += 4) {
            int2 c0 = g_csr[j],     c1 = g_csr[j + 1];
            int2 c2 = g_csr[j + 2], c3 = g_csr[j + 3];
            float2 a0 = reinterpret_cast<const float2*>(xw2 + (long long)c0.x * F)[lane];
            float2 a1 = reinterpret_cast<const float2*>(xw2 + (long long)c1.x * F)[lane];
            float2 a2 = reinterpret_cast<const float2*>(xw2 + (long long)c2.x * F)[lane];
            float2 a3 = reinterpret_cast<const float2*>(xw2 + (long long)c3.x * F)[lane];
            float w0 = __int_as_float(c0.y), w1 = __int_as_float(c1.y);
            float w2 = __int_as_float(c2.y), w3 = __int_as_float(c3.y);
            acc.x = fmaf(a0.x, w0, fmaf(a1.x, w1, fmaf(a2.x, w2, fmaf(a3.x, w3, acc.x))));
            acc.y = fmaf(a0.y, w0, fmaf(a1.y, w1, fmaf(a2.y, w2, fmaf(a3.y, w3, acc.y))));
        }
        for (; j < end; j++) {
            int2 c0 = g_csr[j];
            float w0 = __int_as_float(c0.y);
            float2 a = reinterpret_cast<const float2*>(xw2 + (long long)c0.x * F)[lane];
            acc.x = fmaf(a.x, w0, acc.x);
            acc.y = fmaf(a.y, w0, acc.y);
        }

        __syncwarp();  // prior iteration's hbuf reads complete before rewrite
        hbuf[warp][2 * lane]     = fast_tanhf(acc.x);
        hbuf[warp][2 * lane + 1] = fast_tanhf(acc.y);
        __syncwarp();

        float t0 = sb3[lane];
        float t1 = sb3[lane + 32];
        #pragma unroll
        for (int k = 0; k < 64; k++) {
            float hk = hbuf[warp][k];
            t0 = fmaf(hk, sW3[k * 64 + lane],      t0);
            t1 = fmaf(hk, sW3[k * 64 + lane + 32], t1);
        }
        float o = fmaf(fast_tanhf(t0), sW4[lane],
                       fast_tanhf(t1) * sW4[lane + 32]);
        #pragma unroll
        for (int off = 16; off; off >>= 1)
            o += __shfl_xor_sync(0xFFFFFFFFu, o, off);
        if (lane == 0) out[node] = o + b4v;
    }
}

// ---------------------------------------------------------------------------
// Preload + side-stream + smem opt-in (static init; capture-safe use).
// ---------------------------------------------------------------------------
namespace {
cudaStream_t g_s2 = nullptr;
cudaEvent_t  g_ev_fork = nullptr, g_ev_join = nullptr;
bool g_overlap_ok = false;

struct ModulePreloader {
    ModulePreloader() {
        cudaFree(0);
        void* p = nullptr;
        cudaGetSymbolAddress(&p, g_big1);
        cudaGetSymbolAddress(&p, g_big2);
        cudaFuncAttributes a;
        cudaFuncGetAttributes(&a, (const void*)convert_count_kernel);
        cudaFuncGetAttributes(&a, (const void*)scan_dinv_kernel);
        cudaFuncGetAttributes(&a, (const void*)fill_kernel);
        cudaFuncGetAttributes(&a, (const void*)gemm_tf32_kernel<128>);
        cudaFuncGetAttributes(&a, (const void*)gemm_tf32_kernel<64>);
        cudaFuncGetAttributes(&a, (const void*)gather1_kernel);
        cudaFuncGetAttributes(&a, (const void*)gather_fc_kernel);

        cudaFuncSetAttribute((const void*)gemm_tf32_kernel<128>,
                             cudaFuncAttributeMaxDynamicSharedMemorySize,
                             128 * (128 + 4) * (int)sizeof(float2));
        cudaFuncSetAttribute((const void*)gemm_tf32_kernel<64>,
                             cudaFuncAttributeMaxDynamicSharedMemorySize,
                             128 * (64 + 4) * (int)sizeof(float2));

        bool ok = (cudaStreamCreateWithFlags(&g_s2, cudaStreamNonBlocking) == cudaSuccess);
        ok = ok && (cudaEventCreateWithFlags(&g_ev_fork, cudaEventDisableTiming) == cudaSuccess);
        ok = ok && (cudaEventCreateWithFlags(&g_ev_join, cudaEventDisableTiming) == cudaSuccess);
        g_overlap_ok = ok;
    }
};
ModulePreloader g_preloader;
}

// ---------------------------------------------------------------------------
// Launch
// ---------------------------------------------------------------------------
extern "C" void kernel_launch(void* const* d_in, const int* in_sizes, int n_in,
                              void* d_out, int out_size) {
    const float* x  = (const float*)d_in[0];
    const void*  ei = d_in[1];
    const float* W1 = (const float*)d_in[2];
    const float* b1 = (const float*)d_in[3];
    const float* W2 = (const float*)d_in[4];
    const float* b2 = (const float*)d_in[5];
    const float* W3 = (const float*)d_in[6];
    const float* b3 = (const float*)d_in[7];
    const float* W4 = (const float*)d_in[8];
    const float* b4 = (const float*)d_in[9];
    float* out = (float*)d_out;

    const int H1  = in_sizes[3];            // 128
    const int M   = in_sizes[0] / H1;       // 50000 (FIN == H1 == 128)
    const int E   = in_sizes[1] / 2;        // 800000
    const int T = 256;

    float* big1 = nullptr; float* big2 = nullptr;
    cudaGetSymbolAddress((void**)&big1, g_big1);
    cudaGetSymbolAddress((void**)&big2, g_big2);

    float* xw1 = big1;                      // [M,128]
    float* h1  = big2;                      // [M,128]
    float* xw2 = big1;                      // [M,64] reuses dead xw1

    cudaStream_t sp = (g_overlap_ok ? g_s2 : (cudaStream_t)0);

    if (g_overlap_ok) {
        cudaEventRecord(g_ev_fork, 0);
        cudaStreamWaitEvent(sp, g_ev_fork, 0);
    }

    // --- CSR build chain (stream sp), overlapped with gemm1 ---
    // (deg zeroed by module init on run 1, by prior scan_dinv on replays)
    convert_count_kernel<<<(E + T - 1) / T, T, 0, sp>>>(ei, E);
    scan_dinv_kernel<<<1, 1024, 0, sp>>>(M, E);
    fill_kernel<<<(E + T - 1) / T, T, 0, sp>>>(E);

    // --- gemm1 (tensor cores) on main stream ---
    {
        int smem = 128 * (128 + 4) * (int)sizeof(float2);
        gemm_tf32_kernel<128><<<(M + 127) / 128, T, smem>>>(x, W1, xw1, M);
    }

    if (g_overlap_ok) {
        cudaEventRecord(g_ev_join, sp);
        cudaStreamWaitEvent(0, g_ev_join, 0);
    }

    // --- Layer 1 aggregation: h1 = tanh(gather(xw1) + self + b1) ---
    gather1_kernel<<<(M + 7) / 8, T>>>(xw1, b1, h1, M);

    // --- Layer 2 GEMM ---
    {
        int smem = 128 * (64 + 4) * (int)sizeof(float2);
        gemm_tf32_kernel<64><<<(M + 127) / 128, T, smem>>>(h1, W2, xw2, M);
    }

    // --- Fused gather2 + FC head ---
    gather_fc_kernel<<<782, T>>>(xw2, b2, W3, b3, W4, b4, out, M);
}